// round 1
// baseline (speedup 1.0000x reference)
#include <cuda_runtime.h>
#include <cstdint>
#include <cstddef>

// Problem constants
#define BB   32
#define TT   2048
#define HH   256
#define OBS  64
#define EMB  128
#define G4   1024   // 4*H

// ---------------- device scratch (no allocations allowed) ----------------
__device__ float g_xz[(size_t)BB * TT * G4];   // 256 MB: x-path preactivations
__device__ float g_Wc[OBS * G4];               // W_embed @ kernel
__device__ float g_bc[G4];                     // b_embed @ kernel + bias

// ---------------- kernel 1: fold the two dense layers --------------------
__global__ void prep_kernel(const float* __restrict__ W_embed,
                            const float* __restrict__ b_embed,
                            const float* __restrict__ kern,
                            const float* __restrict__ bias) {
    int j = threadIdx.x;       // 0..1023
    int i = blockIdx.x;        // 0..64 (64 = bc row)
    if (i < OBS) {
        float acc = 0.f;
        #pragma unroll 4
        for (int e = 0; e < EMB; e++)
            acc += W_embed[i * EMB + e] * kern[e * G4 + j];
        g_Wc[i * G4 + j] = acc;
    } else {
        float acc = bias[j];
        #pragma unroll 4
        for (int e = 0; e < EMB; e++)
            acc += b_embed[e] * kern[e * G4 + j];
        g_bc[j] = acc;
    }
}

// ---------------- kernel 2: xz = obs @ Wc + bc ----------------------------
// CTA: 16 rows x 512 cols, 256 threads, 2 cols/thread.
#define K2_ROWS 16
__global__ void __launch_bounds__(256) xz_kernel(const float* __restrict__ obs) {
    __shared__ float obs_s[OBS * K2_ROWS];  // [k][r]
    int bid    = blockIdx.x;
    int colBlk = bid & 1;          // 2 col blocks of 512
    int rowBlk = bid >> 1;         // 4096 row blocks
    int row0   = rowBlk * K2_ROWS;
    int col0   = colBlk * 512;
    int tid    = threadIdx.x;

    for (int idx = tid; idx < OBS * K2_ROWS; idx += 256) {
        int r = idx >> 6, k = idx & 63;
        obs_s[k * K2_ROWS + r] = obs[(size_t)(row0 + r) * OBS + k];
    }
    __syncthreads();

    int c0 = col0 + tid;
    int c1 = c0 + 256;
    float acc0[K2_ROWS], acc1[K2_ROWS];
    #pragma unroll
    for (int r = 0; r < K2_ROWS; r++) { acc0[r] = 0.f; acc1[r] = 0.f; }

    #pragma unroll 4
    for (int k = 0; k < OBS; k++) {
        float w0 = g_Wc[k * G4 + c0];
        float w1 = g_Wc[k * G4 + c1];
        #pragma unroll
        for (int r = 0; r < K2_ROWS; r += 4) {
            float4 o4 = *(const float4*)&obs_s[k * K2_ROWS + r];
            acc0[r + 0] += o4.x * w0; acc0[r + 1] += o4.y * w0;
            acc0[r + 2] += o4.z * w0; acc0[r + 3] += o4.w * w0;
            acc1[r + 0] += o4.x * w1; acc1[r + 1] += o4.y * w1;
            acc1[r + 2] += o4.z * w1; acc1[r + 3] += o4.w * w1;
        }
    }
    float b0 = g_bc[c0], b1 = g_bc[c1];
    #pragma unroll
    for (int r = 0; r < K2_ROWS; r++) {
        size_t row = (size_t)(row0 + r);
        g_xz[row * G4 + c0] = acc0[r] + b0;
        g_xz[row * G4 + c1] = acc1[r] + b1;
    }
}

// ---------------- kernel 3: masked LSTM recurrence ------------------------
// 16 clusters x 8 CTAs. Cluster c owns batches {2c, 2c+1}.
// CTA rank r owns hidden units [r*32, r*32+32) -> 128 gate columns
//   (col = gate*32 + ulocal, global j = gate*256 + r*32 + ulocal).
// R slice fp32 in smem: Rs[col][k], k-contiguous, row stride 260 floats
//   (stride 1040 B -> LDS.128 conflict-free across 32 lanes).
// h: double-buffered full 256-vector per batch in every CTA's smem,
//   all-gathered per step via st.shared::cluster + barrier.cluster.
// c: register-resident in 64 "gate threads" (tid<64 -> (batch, unit)).

#define CLU       8
#define UPC       32
#define CPC       128
#define RS_STRIDE 260
#define SMEM_FLOATS (CPC * RS_STRIDE + 2 * 2 * HH + 2 * 2 * CPC)
#define SMEM_BYTES  (SMEM_FLOATS * 4)

__device__ __forceinline__ void dsmem_store_f32(uint32_t laddr, uint32_t peer, float v) {
    asm volatile(
        "{\n\t.reg .b32 ra;\n\t"
        "mapa.shared::cluster.u32 ra, %0, %1;\n\t"
        "st.shared::cluster.f32 [ra], %2;\n\t}"
        :: "r"(laddr), "r"(peer), "f"(v) : "memory");
}

__device__ __forceinline__ void cluster_sync_() {
    asm volatile("barrier.cluster.arrive.aligned;" ::: "memory");
    asm volatile("barrier.cluster.wait.aligned;" ::: "memory");
}

extern __shared__ float smem3[];

__global__ void __launch_bounds__(256, 1) __cluster_dims__(CLU, 1, 1)
rec_kernel(const float* __restrict__ S, const float* __restrict__ M,
           const float* __restrict__ rec, float* __restrict__ out) {
    float* Rs    = smem3;                       // CPC*RS_STRIDE floats
    float* hbuf  = Rs + CPC * RS_STRIDE;        // [parity][batch][256]
    float* zpart = hbuf + 2 * 2 * HH;           // [batch][khalf][128]

    const int tid  = threadIdx.x;
    const int rank = blockIdx.x & (CLU - 1);
    const int cid  = blockIdx.x / CLU;
    const int b0g  = cid * 2;

    // Load R slice (permuted: gates blocked per owned unit range)
    for (int idx = tid; idx < HH * CPC; idx += 256) {
        int k = idx >> 7, col = idx & 127;
        int gate = col >> 5, ul = col & 31;
        Rs[col * RS_STRIDE + k] = rec[k * G4 + gate * HH + rank * UPC + ul];
    }
    // Init h (parity 0) from S = [h | c]
    for (int idx = tid; idx < 2 * HH; idx += 256) {
        int b = idx >> 8, k = idx & 255;
        hbuf[b * HH + k] = S[(size_t)(b0g + b) * (2 * HH) + k];
    }
    const int gb = tid >> 5, gu = tid & 31;   // gate-thread coords (tid<64)
    float c_st = 0.f;
    if (tid < 64)
        c_st = S[(size_t)(b0g + gb) * (2 * HH) + HH + rank * UPC + gu];
    __syncthreads();

    const int   col   = tid & 127;
    const int   khalf = tid >> 7;
    const float* Rcol = Rs + col * RS_STRIDE + khalf * 128;

    for (int t = 0; t < TT; t++) {
        const int p = t & 1;

        // Prefetch x-path and mask for this step (h-independent)
        float xi = 0.f, xf = 0.f, xg = 0.f, xo = 0.f, mval = 0.f;
        size_t row = 0;
        if (tid < 64) {
            row = (size_t)(b0g + gb) * TT + (size_t)t;
            const float* xr = g_xz + row * G4 + rank * UPC + gu;
            xi = xr[0 * HH]; xf = xr[1 * HH]; xg = xr[2 * HH]; xo = xr[3 * HH];
            mval = M[row];
        }

        // Recurrent matvec: z_rec[col] for both batches over half the K range
        const float* H0 = hbuf + p * 2 * HH + khalf * 128;
        const float* H1 = H0 + HH;
        float4 a0 = {0.f, 0.f, 0.f, 0.f};
        float4 a1 = {0.f, 0.f, 0.f, 0.f};
        #pragma unroll 8
        for (int k = 0; k < 128; k += 4) {
            float4 r  = *(const float4*)(Rcol + k);
            float4 h0 = *(const float4*)(H0 + k);
            float4 h1 = *(const float4*)(H1 + k);
            a0.x += r.x * h0.x; a0.y += r.y * h0.y;
            a0.z += r.z * h0.z; a0.w += r.w * h0.w;
            a1.x += r.x * h1.x; a1.y += r.y * h1.y;
            a1.z += r.z * h1.z; a1.w += r.w * h1.w;
        }
        zpart[(0 * 2 + khalf) * 128 + col] = (a0.x + a0.y) + (a0.z + a0.w);
        zpart[(2 + khalf) * 128 + col]     = (a1.x + a1.y) + (a1.z + a1.w);
        __syncthreads();

        if (tid < 64) {
            const float keep = 1.f - mval;
            const int zb = gb * 2;
            float zi = xi + keep * (zpart[zb * 128 + gu]       + zpart[(zb + 1) * 128 + gu]);
            float zf = xf + keep * (zpart[zb * 128 + 32 + gu]  + zpart[(zb + 1) * 128 + 32 + gu]);
            float zg = xg + keep * (zpart[zb * 128 + 64 + gu]  + zpart[(zb + 1) * 128 + 64 + gu]);
            float zo = xo + keep * (zpart[zb * 128 + 96 + gu]  + zpart[(zb + 1) * 128 + 96 + gu]);

            float ig = 1.f / (1.f + __expf(-zi));
            float fg = 1.f / (1.f + __expf(-zf));
            float gg = tanhf(zg);
            float og = 1.f / (1.f + __expf(-zo));

            float c = keep * c_st;
            c = fg * c + ig * gg;
            c_st = c;
            float hh = og * tanhf(c);

            out[row * HH + rank * UPC + gu] = hh;

            // broadcast h slice into every cluster CTA's hbuf[p^1]
            uint32_t laddr = (uint32_t)__cvta_generic_to_shared(
                &hbuf[(p ^ 1) * 2 * HH + gb * HH + rank * UPC + gu]);
            #pragma unroll
            for (uint32_t peer = 0; peer < CLU; peer++)
                dsmem_store_f32(laddr, peer, hh);
        }
        cluster_sync_();   // orders DSMEM stores (release/acquire) + step barrier
    }
}

// ---------------- launch ---------------------------------------------------
extern "C" void kernel_launch(void* const* d_in, const int* in_sizes, int n_in,
                              void* d_out, int out_size) {
    const float* obs     = (const float*)d_in[0];
    const float* S       = (const float*)d_in[1];
    const float* M       = (const float*)d_in[2];
    const float* W_embed = (const float*)d_in[3];
    const float* b_embed = (const float*)d_in[4];
    const float* kern    = (const float*)d_in[5];
    const float* rec     = (const float*)d_in[6];
    const float* bias    = (const float*)d_in[7];
    float* out = (float*)d_out;

    cudaFuncSetAttribute(rec_kernel,
                         cudaFuncAttributeMaxDynamicSharedMemorySize, SMEM_BYTES);

    prep_kernel<<<65, 1024>>>(W_embed, b_embed, kern, bias);
    xz_kernel<<<8192, 256>>>(obs);
    rec_kernel<<<128, 256, SMEM_BYTES>>>(S, M, rec, out);
}